// round 8
// baseline (speedup 1.0000x reference)
#include <cuda_runtime.h>
#include <cstdint>
#include <math_constants.h>

#define NN    169343
#define EMAX  2600000
#define EPSV  1e-5f
#define NB_SCAN ((NN + 1023) / 1024)   // 166

// ---------------- scratch (static device globals; no allocs) ----------------
__device__ int   g_src[EMAX];
__device__ int   g_dst[EMAX];
__device__ int   g_cnt[NN];        // in-degree (no self loop)
__device__ int   g_cur[NN];        // fill cursor
__device__ int   g_rowptr[NN];     // exclusive prefix sum of g_cnt
__device__ int   g_bsum[NB_SCAN];
__device__ float g_dinv[NN];       // rsqrt(deg), deg = cnt+1
__device__ float g_snorm[NN];      // 1/deg
__device__ int   g_csr_src[EMAX];
__device__ float g_csr_w[EMAX];
__device__ float g_bufA[(size_t)NN * 256];   // GEMM output h
__device__ float g_bufB[(size_t)NN * 256];   // aggregated+activated
__device__ float g_buf40[(size_t)NN * 40];   // h2 @ W3
__device__ int   g_is64;

static inline int cdiv(long a, long b) { return (int)((a + b - 1) / b); }

// ---------------- prep ----------------
__global__ void k_zero() {
    int i = blockIdx.x * blockDim.x + threadIdx.x;
    if (i < NN) { g_cnt[i] = 0; g_cur[i] = 0; }
}

// int64 vs int32: int32 buffer read as int64 pairs two ids -> >= 2^32.
__global__ void k_detect(const long long* __restrict__ p) {
    if (threadIdx.x == 0) {
        int ok = 1;
        for (int i = 0; i < 64; i++) {
            long long v = p[i];
            if (v < 0 || v >= NN) { ok = 0; break; }
        }
        g_is64 = ok;
    }
}

__global__ void k_count(const void* __restrict__ ei, int E) {
    int e = blockIdx.x * blockDim.x + threadIdx.x;
    if (e >= E) return;
    long long s, d;
    if (g_is64) {
        const long long* p = (const long long*)ei;
        s = p[e]; d = p[(size_t)E + e];
    } else {
        const int* p = (const int*)ei;
        s = p[e]; d = p[(size_t)E + e];
    }
    if ((unsigned long long)s < (unsigned long long)NN &&
        (unsigned long long)d < (unsigned long long)NN) {
        g_src[e] = (int)s; g_dst[e] = (int)d;
        atomicAdd(&g_cnt[(int)d], 1);
    } else {
        g_src[e] = -1; g_dst[e] = -1;   // skip invalid/padding edges
    }
}

// ---------------- two-level exclusive scan over g_cnt -> g_rowptr ----------
__global__ void k_scan1() {
    __shared__ int sh[256];
    int b = blockIdx.x, t = threadIdx.x;
    int base = b * 1024 + t * 4;
    int v[4];
#pragma unroll
    for (int j = 0; j < 4; j++) v[j] = (base + j < NN) ? g_cnt[base + j] : 0;
    int ts = v[0] + v[1] + v[2] + v[3];
    sh[t] = ts;
    __syncthreads();
#pragma unroll
    for (int off = 1; off < 256; off <<= 1) {
        int x = (t >= off) ? sh[t - off] : 0;
        __syncthreads();
        sh[t] += x;
        __syncthreads();
    }
    int excl = sh[t] - ts;     // exclusive prefix of this thread's group
    int run = excl;
#pragma unroll
    for (int j = 0; j < 4; j++) {
        if (base + j < NN) g_rowptr[base + j] = run;
        run += v[j];
    }
    if (t == 255) g_bsum[b] = sh[255];
}

__global__ void k_scan2(int nb) {
    __shared__ int sh[256];
    int t = threadIdx.x;
    int v = (t < nb) ? g_bsum[t] : 0;
    sh[t] = v;
    __syncthreads();
#pragma unroll
    for (int off = 1; off < 256; off <<= 1) {
        int x = (t >= off) ? sh[t - off] : 0;
        __syncthreads();
        sh[t] += x;
        __syncthreads();
    }
    if (t < nb) g_bsum[t] = sh[t] - v;  // exclusive
}

__global__ void k_scan3() {
    int b = blockIdx.x, t = threadIdx.x;
    int add = g_bsum[b];
    int base = b * 1024 + t * 4;
#pragma unroll
    for (int j = 0; j < 4; j++)
        if (base + j < NN) g_rowptr[base + j] += add;
}

__global__ void k_norms() {
    int i = blockIdx.x * blockDim.x + threadIdx.x;
    if (i >= NN) return;
    float deg = (float)(g_cnt[i] + 1);
    g_dinv[i]  = rsqrtf(deg);
    g_snorm[i] = 1.0f / deg;
}

__global__ void k_fill(int E) {
    int e = blockIdx.x * blockDim.x + threadIdx.x;
    if (e >= E) return;
    int d = g_dst[e];
    if (d < 0) return;
    int s = g_src[e];
    int slot = g_rowptr[d] + atomicAdd(&g_cur[d], 1);
    g_csr_src[slot] = s;
    g_csr_w[slot]   = g_dinv[s] * g_dinv[d];
}

// ---------------- aggregation (warp per node), fused BN+ReLU ---------------
// Y[n] = relu(BN(sum_in w*X[src] + X[n]*snorm + bias))     (BN=true)
// Y[n] =        sum_in w*X[src] + X[n]*snorm + bias        (BN=false)
template <bool BN>
__global__ void k_agg256(const float* __restrict__ X, float* __restrict__ Y,
                         const float* __restrict__ bias,
                         const float* __restrict__ gamma, const float* __restrict__ beta,
                         const float* __restrict__ mean,  const float* __restrict__ var) {
    int node = (int)((blockIdx.x * (long)blockDim.x + threadIdx.x) >> 5);
    int lane = threadIdx.x & 31;
    if (node >= NN) return;
    int start = g_rowptr[node];
    int cnt   = g_cnt[node];

    float4 a0 = make_float4(0.f, 0.f, 0.f, 0.f);
    float4 a1 = make_float4(0.f, 0.f, 0.f, 0.f);
    for (int i = 0; i < cnt; i++) {
        int   s = g_csr_src[start + i];
        float w = g_csr_w[start + i];
        const float4* xs = (const float4*)(X + (size_t)s * 256);
        float4 v0 = xs[lane], v1 = xs[lane + 32];
        a0.x += v0.x * w; a0.y += v0.y * w; a0.z += v0.z * w; a0.w += v0.w * w;
        a1.x += v1.x * w; a1.y += v1.y * w; a1.z += v1.z * w; a1.w += v1.w * w;
    }
    {
        float sn = g_snorm[node];
        const float4* xd = (const float4*)(X + (size_t)node * 256);
        float4 v0 = xd[lane], v1 = xd[lane + 32];
        a0.x += v0.x * sn; a0.y += v0.y * sn; a0.z += v0.z * sn; a0.w += v0.w * sn;
        a1.x += v1.x * sn; a1.y += v1.y * sn; a1.z += v1.z * sn; a1.w += v1.w * sn;
    }
    float4 b0 = ((const float4*)bias)[lane];
    float4 b1 = ((const float4*)bias)[lane + 32];
    a0.x += b0.x; a0.y += b0.y; a0.z += b0.z; a0.w += b0.w;
    a1.x += b1.x; a1.y += b1.y; a1.z += b1.z; a1.w += b1.w;

    if (BN) {
        float4 gm0 = ((const float4*)gamma)[lane],  gm1 = ((const float4*)gamma)[lane + 32];
        float4 bt0 = ((const float4*)beta)[lane],   bt1 = ((const float4*)beta)[lane + 32];
        float4 mn0 = ((const float4*)mean)[lane],   mn1 = ((const float4*)mean)[lane + 32];
        float4 vr0 = ((const float4*)var)[lane],    vr1 = ((const float4*)var)[lane + 32];
        a0.x = fmaxf((a0.x - mn0.x) * rsqrtf(vr0.x + EPSV) * gm0.x + bt0.x, 0.f);
        a0.y = fmaxf((a0.y - mn0.y) * rsqrtf(vr0.y + EPSV) * gm0.y + bt0.y, 0.f);
        a0.z = fmaxf((a0.z - mn0.z) * rsqrtf(vr0.z + EPSV) * gm0.z + bt0.z, 0.f);
        a0.w = fmaxf((a0.w - mn0.w) * rsqrtf(vr0.w + EPSV) * gm0.w + bt0.w, 0.f);
        a1.x = fmaxf((a1.x - mn1.x) * rsqrtf(vr1.x + EPSV) * gm1.x + bt1.x, 0.f);
        a1.y = fmaxf((a1.y - mn1.y) * rsqrtf(vr1.y + EPSV) * gm1.y + bt1.y, 0.f);
        a1.z = fmaxf((a1.z - mn1.z) * rsqrtf(vr1.z + EPSV) * gm1.z + bt1.z, 0.f);
        a1.w = fmaxf((a1.w - mn1.w) * rsqrtf(vr1.w + EPSV) * gm1.w + bt1.w, 0.f);
    }
    float4* yd = (float4*)(Y + (size_t)node * 256);
    yd[lane] = a0;
    yd[lane + 32] = a1;
}

// ---------------- layer-3 aggregation + bias + log_softmax (warp/node) -----
__global__ void k_agg40_lsm(const float* __restrict__ X, float* __restrict__ out,
                            const float* __restrict__ b3) {
    int node = (int)((blockIdx.x * (long)blockDim.x + threadIdx.x) >> 5);
    int lane = threadIdx.x & 31;
    if (node >= NN) return;
    int start = g_rowptr[node];
    int cnt   = g_cnt[node];

    float a0 = 0.f, a1 = 0.f;   // feature lane, feature lane+32 (lane<8)
    for (int i = 0; i < cnt; i++) {
        int   s = g_csr_src[start + i];
        float w = g_csr_w[start + i];
        const float* xs = X + (size_t)s * 40;
        a0 += xs[lane] * w;
        if (lane < 8) a1 += xs[lane + 32] * w;
    }
    {
        float sn = g_snorm[node];
        const float* xd = X + (size_t)node * 40;
        a0 += xd[lane] * sn;
        if (lane < 8) a1 += xd[lane + 32] * sn;
    }
    a0 += b3[lane];
    if (lane < 8) a1 += b3[lane + 32];

    float v1 = (lane < 8) ? a1 : -CUDART_INF_F;
    float mx = fmaxf(a0, v1);
#pragma unroll
    for (int o = 16; o > 0; o >>= 1) mx = fmaxf(mx, __shfl_xor_sync(0xffffffffu, mx, o));
    float sum = expf(a0 - mx) + ((lane < 8) ? expf(a1 - mx) : 0.f);
#pragma unroll
    for (int o = 16; o > 0; o >>= 1) sum += __shfl_xor_sync(0xffffffffu, sum, o);
    float lg = mx + logf(sum);
    out[(size_t)node * 40 + lane] = a0 - lg;
    if (lane < 8) out[(size_t)node * 40 + lane + 32] = a1 - lg;
}

// ---------------- SGEMM fp32: C = A @ W ----------------
__global__ __launch_bounds__(256) void k_sgemm(
    const float* __restrict__ A, const float* __restrict__ W,
    float* __restrict__ C, int M, int K, int Ncol)
{
    __shared__ float As[16][129];
    __shared__ float Bs[16][64];

    const int tid = threadIdx.x;
    const int bm = blockIdx.y * 128;
    const int bn = blockIdx.x * 64;
    const int ry = tid >> 4;
    const int cx = tid & 15;

    float acc[8][4];
#pragma unroll
    for (int i = 0; i < 8; i++)
#pragma unroll
        for (int j = 0; j < 4; j++) acc[i][j] = 0.f;

    for (int k0 = 0; k0 < K; k0 += 16) {
#pragma unroll
        for (int l = 0; l < 2; l++) {
            int idx = tid + l * 256;
            int r  = idx >> 2;
            int c4 = (idx & 3) << 2;
            int grow = bm + r;
            float4 v = make_float4(0.f, 0.f, 0.f, 0.f);
            if (grow < M) v = *(const float4*)&A[(size_t)grow * K + k0 + c4];
            As[c4 + 0][r] = v.x; As[c4 + 1][r] = v.y;
            As[c4 + 2][r] = v.z; As[c4 + 3][r] = v.w;
        }
        {
            int r  = tid >> 4;
            int c4 = (tid & 15) << 2;
            int gc = bn + c4;
            float4 v = make_float4(0.f, 0.f, 0.f, 0.f);
            if (gc < Ncol) v = *(const float4*)&W[(size_t)(k0 + r) * Ncol + gc];
            *(float4*)&Bs[r][c4] = v;
        }
        __syncthreads();
#pragma unroll
        for (int k = 0; k < 16; k++) {
            float a[8];
#pragma unroll
            for (int i = 0; i < 8; i++) a[i] = As[k][ry + (i << 4)];
            float4 bv = *(const float4*)&Bs[k][cx << 2];
#pragma unroll
            for (int i = 0; i < 8; i++) {
                acc[i][0] += a[i] * bv.x;
                acc[i][1] += a[i] * bv.y;
                acc[i][2] += a[i] * bv.z;
                acc[i][3] += a[i] * bv.w;
            }
        }
        __syncthreads();
    }

    int colbase = bn + (cx << 2);
    if (colbase >= Ncol) return;
#pragma unroll
    for (int i = 0; i < 8; i++) {
        int row = bm + ry + (i << 4);
        if (row < M) {
            float4 o = make_float4(acc[i][0], acc[i][1], acc[i][2], acc[i][3]);
            *(float4*)&C[(size_t)row * Ncol + colbase] = o;
        }
    }
}

// ---------------- launch ----------------
extern "C" void kernel_launch(void* const* d_in, const int* in_sizes, int n_in,
                              void* d_out, int out_size) {
    const float* x   = (const float*)d_in[0];
    const void*  ei  = d_in[1];
    const float* W1  = (const float*)d_in[2];
    const float* b1  = (const float*)d_in[3];
    const float* g1  = (const float*)d_in[4];
    const float* be1 = (const float*)d_in[5];
    const float* m1  = (const float*)d_in[6];
    const float* v1  = (const float*)d_in[7];
    const float* W2  = (const float*)d_in[8];
    const float* b2  = (const float*)d_in[9];
    const float* g2  = (const float*)d_in[10];
    const float* be2 = (const float*)d_in[11];
    const float* m2  = (const float*)d_in[12];
    const float* v2  = (const float*)d_in[13];
    const float* W3  = (const float*)d_in[14];
    const float* b3  = (const float*)d_in[15];

    int E = in_sizes[1] / 2;
    if (E > EMAX) E = EMAX;

    float* out = (float*)d_out;
    float* emb;
    if ((long)out_size >= (long)NN * 296) {
        emb = out + (size_t)NN * 40;   // (out[N,40], emb[N,256]) concatenated
    } else {
        void* p = nullptr;
        cudaGetSymbolAddress(&p, g_bufB);
        emb = (float*)p;
    }

    // ---- prep: CSR by destination ----
    k_zero<<<cdiv(NN, 256), 256>>>();
    k_detect<<<1, 32>>>((const long long*)ei);
    k_count<<<cdiv(E, 256), 256>>>(ei, E);
    k_scan1<<<NB_SCAN, 256>>>();
    k_scan2<<<1, 256>>>(NB_SCAN);
    k_scan3<<<NB_SCAN, 256>>>();
    k_norms<<<cdiv(NN, 256), 256>>>();
    k_fill<<<cdiv(E, 256), 256>>>(E);

    const int warpsGrid = cdiv((long)NN * 32, 256);

    // ---- layer 1: h = x@W1; z = agg(h)+self+b1; h1 = relu(BN(z)) ----
    k_sgemm<<<dim3(4, cdiv(NN, 128)), 256>>>(x, W1, g_bufA, NN, 128, 256);
    k_agg256<true><<<warpsGrid, 256>>>(g_bufA, g_bufB, b1, g1, be1, m1, v1);

    // ---- layer 2 ----
    k_sgemm<<<dim3(4, cdiv(NN, 128)), 256>>>(g_bufB, W2, g_bufA, NN, 256, 256);
    k_agg256<true><<<warpsGrid, 256>>>(g_bufA, emb, b2, g2, be2, m2, v2);

    // ---- layer 3 ----
    k_sgemm<<<dim3(1, cdiv(NN, 128)), 256>>>(emb, W3, g_buf40, NN, 256, 40);
    k_agg40_lsm<<<warpsGrid, 256>>>(g_buf40, out, b3);
}